// round 13
// baseline (speedup 1.0000x reference)
#include <cuda_runtime.h>
#include <cstdint>

// Lorenz Taylor-step elementwise map. (N,3) f32 -> (N,3) f32.
// R13 = R9 shape exactly (8 rows/thread, 3x 256-bit v8 ld/st, 2048x256 launch)
// with the L2 policy INVERTED:
//   - input:  ld.global.nc.L2::evict_first  (stream reads from DRAM at read BW)
//   - output: st.global.L2::evict_last      (48MB output stays L2-resident,
//     re-dirtied in place every graph replay -> ~zero DRAM writes steady-state)
// Rationale: all configs converge on dur = 48MB / ~3.2TB/s DRAM *write* drain.
// DRAM read bandwidth is much higher than write bandwidth; trade writes for reads.

struct V8 { float f[8]; };

__device__ __forceinline__ V8 ldg256_stream(const void* p) {
    V8 v;
    asm volatile("ld.global.nc.L2::evict_first.v8.b32 {%0,%1,%2,%3,%4,%5,%6,%7}, [%8];"
                 : "=f"(v.f[0]), "=f"(v.f[1]), "=f"(v.f[2]), "=f"(v.f[3]),
                   "=f"(v.f[4]), "=f"(v.f[5]), "=f"(v.f[6]), "=f"(v.f[7])
                 : "l"(p));
    return v;
}
__device__ __forceinline__ void stg256_keep(void* p, const V8& v) {
    asm volatile("st.global.L2::evict_last.v8.b32 [%0], {%1,%2,%3,%4,%5,%6,%7,%8};"
                 :: "l"(p),
                    "f"(v.f[0]), "f"(v.f[1]), "f"(v.f[2]), "f"(v.f[3]),
                    "f"(v.f[4]), "f"(v.f[5]), "f"(v.f[6]), "f"(v.f[7])
                 : "memory");
}

__device__ __forceinline__ void lorenz_row(float yi0, float yi1, float yi2,
                                           float& o0, float& o1, float& o2) {
    const float h    = 0.01f;
    const float h2   = h * h;
    const float h3   = h2 * h;
    const float a0   = 0.5f;
    const float a1   = 1.0f / 6.0f;
    const float a2   = 1.0f / 6.0f;
    const float a4   = 3.0f / 24.0f;
    const float a5   = 1.0f / 24.0f;
    const float a6   = 1.0f / 24.0f;
    const float beta = 8.0f / 3.0f;

    const float y0 = 10.0f * yi0;
    const float y1 = 10.0f * yi1;
    const float y2 = 10.0f * yi2;

    const float f0 = 10.0f * y1 - 10.0f * y0;
    const float f1 = 28.0f * y0 - y0 * y2 - y1;
    const float f2 = y0 * y1 - beta * y2;

    const float c10 = 28.0f - y2;

    const float dff0 = -10.0f * f0 + 10.0f * f1;
    const float dff1 = c10 * f0 - f1 - y0 * f2;
    const float dff2 = y1 * f0 + y0 * f1 - beta * f2;

    const float dfdff0 = -10.0f * dff0 + 10.0f * dff1;
    const float dfdff1 = c10 * dff0 - dff1 - y0 * dff2;
    const float dfdff2 = y1 * dff0 + y0 * dff1 - beta * dff2;

    const float ddfff1 = -2.0f * f0 * f2;
    const float ddfff2 =  2.0f * f0 * f1;

    const float ddfdfff1 = -dff0 * f2 - dff2 * f0;
    const float ddfdfff2 =  dff0 * f1 + dff1 * f0;

    const float dfddfff0 = 10.0f * ddfff1;
    const float dfddfff1 = -ddfff1 - y0 * ddfff2;
    const float dfddfff2 = y0 * f1 - beta * ddfff2;

    const float dfdfdff0 = -10.0f * dfdff0 + 10.0f * dfdff1;
    const float dfdfdff1 = c10 * dfdff0 - dfdff1 - y0 * dfdff2;
    const float dfdfdff2 = y1 * dfdff0 + y0 * dfdff1 - beta * dfdff2;

    const float c0 = f0 + a0 * h * dff0
                        + a2 * h2 * dfdff0
                        + a5 * h3 * dfddfff0
                        + a6 * h3 * dfdfdff0;
    const float c1 = f1 + a0 * h * dff1
                        + a1 * h2 * ddfff1
                        + a2 * h2 * dfdff1
                        + a4 * h3 * ddfdfff1
                        + a5 * h3 * dfddfff1
                        + a6 * h3 * dfdfdff1;
    const float c2 = f2 + a0 * h * dff2
                        + a1 * h2 * ddfff2
                        + a2 * h2 * dfdff2
                        + a4 * h3 * ddfdfff2
                        + a5 * h3 * dfddfff2
                        + a6 * h3 * dfdfdff2;

    o0 = c0 * 0.1f;
    o1 = c1 * 0.1f;
    o2 = c2 * 0.1f;
}

// Each thread: 8 rows = 24 floats = 3 x 256-bit loads / stores.
__global__ void __launch_bounds__(256, 6)
lorenz_v8i(const float* __restrict__ in, float* __restrict__ out, int n_oct) {
    const int t = blockIdx.x * blockDim.x + threadIdx.x;
    if (t >= n_oct) return;

    const size_t base = (size_t)t * 24;   // floats

    const V8 a = ldg256_stream(in + base);
    const V8 b = ldg256_stream(in + base + 8);
    const V8 c = ldg256_stream(in + base + 16);

    V8 oa, ob, oc;
    lorenz_row(a.f[0], a.f[1], a.f[2], oa.f[0], oa.f[1], oa.f[2]);
    lorenz_row(a.f[3], a.f[4], a.f[5], oa.f[3], oa.f[4], oa.f[5]);
    lorenz_row(a.f[6], a.f[7], b.f[0], oa.f[6], oa.f[7], ob.f[0]);
    lorenz_row(b.f[1], b.f[2], b.f[3], ob.f[1], ob.f[2], ob.f[3]);
    lorenz_row(b.f[4], b.f[5], b.f[6], ob.f[4], ob.f[5], ob.f[6]);
    lorenz_row(b.f[7], c.f[0], c.f[1], ob.f[7], oc.f[0], oc.f[1]);
    lorenz_row(c.f[2], c.f[3], c.f[4], oc.f[2], oc.f[3], oc.f[4]);
    lorenz_row(c.f[5], c.f[6], c.f[7], oc.f[5], oc.f[6], oc.f[7]);

    stg256_keep(out + base,      oa);
    stg256_keep(out + base + 8,  ob);
    stg256_keep(out + base + 16, oc);
}

extern "C" void kernel_launch(void* const* d_in, const int* in_sizes, int n_in,
                              void* d_out, int out_size) {
    const float* y = (const float*)d_in[0];
    float* out = (float*)d_out;

    const long long n_elems = in_sizes[0];   // N * 3
    const long long n_rows  = n_elems / 3;   // N = 4194304
    const int n_oct = (int)(n_rows / 8);     // 524288 threads

    const int threads = 256;
    const int blocks = (n_oct + threads - 1) / threads;   // 2048
    lorenz_v8i<<<blocks, threads>>>(y, out, n_oct);
}

// round 14
// speedup vs baseline: 1.1358x; 1.1358x over previous
#include <cuda_runtime.h>
#include <cstdint>

// Lorenz Taylor-step elementwise map. (N,3) f32 -> (N,3) f32.
// R14 = R9 memory config FROZEN (unique optimum found over R8-R13):
//   2048x256 one-shot launch, 8 rows/thread,
//   3x ld.global.nc.L2::evict_last.v8  (input L2-resident across replays)
//   3x st.global.L2::evict_first.v8    (output streamed to DRAM)
// NEW: math rewritten in scaled variables (F=f/10, G=ddfff/100, ...) so the
// 10x input scale and /10 output scale fold into 6 constants. ~15% fewer
// FFMAs, shorter chains. Verified algebraically identical (incl. the y0*f1
// quirk in dfddfff[2] -> a*F1).

struct V8 { float f[8]; };

__device__ __forceinline__ V8 ldg256_keep(const void* p) {
    V8 v;
    asm volatile("ld.global.nc.L2::evict_last.v8.b32 {%0,%1,%2,%3,%4,%5,%6,%7}, [%8];"
                 : "=f"(v.f[0]), "=f"(v.f[1]), "=f"(v.f[2]), "=f"(v.f[3]),
                   "=f"(v.f[4]), "=f"(v.f[5]), "=f"(v.f[6]), "=f"(v.f[7])
                 : "l"(p));
    return v;
}
__device__ __forceinline__ void stg256_stream(void* p, const V8& v) {
    asm volatile("st.global.L2::evict_first.v8.b32 [%0], {%1,%2,%3,%4,%5,%6,%7,%8};"
                 :: "l"(p),
                    "f"(v.f[0]), "f"(v.f[1]), "f"(v.f[2]), "f"(v.f[3]),
                    "f"(v.f[4]), "f"(v.f[5]), "f"(v.f[6]), "f"(v.f[7])
                 : "memory");
}

// Scaled-variable Lorenz Taylor step. Inputs a,b,c are the RAW yi values.
__device__ __forceinline__ void lorenz_row(float a, float b, float c,
                                           float& o0, float& o1, float& o2) {
    const float beta = 8.0f / 3.0f;
    // folded coefficients (h = 0.01)
    const float C0 = 0.005f;                 // a0*h
    const float CG = 1.6666667e-4f;          // 10*a1*h^2
    const float C2 = 1.6666667e-5f;          // a2*h^2
    const float CH = 1.25e-6f;               // 10*a4*h^3
    const float CK = 4.1666667e-7f;          // 10*a5*h^3
    const float C6 = 4.1666667e-8f;          // a6*h^3

    const float u = 10.0f * a;               // y0
    const float w = 10.0f * b;               // y1
    const float t = 28.0f - 10.0f * c;       // 28 - y2

    // F = f/10
    const float F0 = w - u;
    const float F1 = t * a - b;
    const float F2 = u * b - beta * c;

    // J(v) = jac at y applied to v (exact jacobian, linear in v)
    // DFF = J(F) = dff/10
    const float DFF0 = 10.0f * (F1 - F0);
    const float DFF1 = t * F0 - F1 - u * F2;
    const float DFF2 = w * F0 + u * F1 - beta * F2;

    // D2 = J(DFF) = dfdff/10
    const float D20 = 10.0f * (DFF1 - DFF0);
    const float D21 = t * DFF0 - DFF1 - u * DFF2;
    const float D22 = w * DFF0 + u * DFF1 - beta * DFF2;

    // D3 = J(D2) = dfdfdff/10
    const float D30 = 10.0f * (D21 - D20);
    const float D31 = t * D20 - D21 - u * D22;
    const float D32 = w * D20 + u * D21 - beta * D22;

    // G = ddfff/100 = (0, -2 F0 F2, 2 F0 F1)
    const float m  = 2.0f * F0;
    const float G1 = -m * F2;
    const float G2 =  m * F1;

    // H = ddfdfff/100 = (0, -DFF0 F2 - DFF2 F0, DFF0 F1 + DFF1 F0)
    const float H1 = -DFF0 * F2 - DFF2 * F0;
    const float H2 =  DFF0 * F1 + DFF1 * F0;

    // K = dfddfff/100 = (10 G1, -G1 - u G2, a F1 - beta G2)   [quirk: a*F1]
    const float K1 = 10.0f * G1;
    const float K2 = -G1 - u * G2;
    const float K3 = a * F1 - beta * G2;

    o0 = F0 + C0 * DFF0 + C2 * D20 + CK * K1 + C6 * D30;
    o1 = F1 + C0 * DFF1 + CG * G1 + C2 * D21 + CH * H1 + CK * K2 + C6 * D31;
    o2 = F2 + C0 * DFF2 + CG * G2 + C2 * D22 + CH * H2 + CK * K3 + C6 * D32;
}

// Each thread: 8 rows = 24 floats = 3 x 256-bit loads / stores (R9 shape).
__global__ void __launch_bounds__(256, 6)
lorenz_v8r(const float* __restrict__ in, float* __restrict__ out, int n_oct) {
    const int t = blockIdx.x * blockDim.x + threadIdx.x;
    if (t >= n_oct) return;

    const size_t base = (size_t)t * 24;   // floats

    const V8 a = ldg256_keep(in + base);
    const V8 b = ldg256_keep(in + base + 8);
    const V8 c = ldg256_keep(in + base + 16);

    V8 oa, ob, oc;
    lorenz_row(a.f[0], a.f[1], a.f[2], oa.f[0], oa.f[1], oa.f[2]);
    lorenz_row(a.f[3], a.f[4], a.f[5], oa.f[3], oa.f[4], oa.f[5]);
    lorenz_row(a.f[6], a.f[7], b.f[0], oa.f[6], oa.f[7], ob.f[0]);
    lorenz_row(b.f[1], b.f[2], b.f[3], ob.f[1], ob.f[2], ob.f[3]);
    lorenz_row(b.f[4], b.f[5], b.f[6], ob.f[4], ob.f[5], ob.f[6]);
    lorenz_row(b.f[7], c.f[0], c.f[1], ob.f[7], oc.f[0], oc.f[1]);
    lorenz_row(c.f[2], c.f[3], c.f[4], oc.f[2], oc.f[3], oc.f[4]);
    lorenz_row(c.f[5], c.f[6], c.f[7], oc.f[5], oc.f[6], oc.f[7]);

    stg256_stream(out + base,      oa);
    stg256_stream(out + base + 8,  ob);
    stg256_stream(out + base + 16, oc);
}

extern "C" void kernel_launch(void* const* d_in, const int* in_sizes, int n_in,
                              void* d_out, int out_size) {
    const float* y = (const float*)d_in[0];
    float* out = (float*)d_out;

    const long long n_elems = in_sizes[0];   // N * 3
    const long long n_rows  = n_elems / 3;   // N = 4194304
    const int n_oct = (int)(n_rows / 8);     // 524288 threads

    const int threads = 256;
    const int blocks = (n_oct + threads - 1) / threads;   // 2048
    lorenz_v8r<<<blocks, threads>>>(y, out, n_oct);
}